// round 15
// baseline (speedup 1.0000x reference)
#include <cuda_runtime.h>
#include <cuda_fp16.h>
#include <math.h>
#include <cstdint>

// ---------------------------------------------------------------------------
// Problem constants
// ---------------------------------------------------------------------------
#define BATCH 4
#define SEQ   4096
#define DIN   2048
#define PAIRS 256
#define MROWS (BATCH*SEQ)      // 16384
#define NCHUNK 256
#define TCHUNK (SEQ/NCHUNK)    // 16

// Scratch (device globals: no allocation allowed)
__device__ float g_delta[MROWS * PAIRS];           // 16.8 MB [m][p]
__device__ float g_csum [BATCH * NCHUNK * PAIRS];  // [b][c][p]
__device__ float g_coff [BATCH * NCHUNK * PAIRS];  // [b][c][p]
__device__ __half g_Wh[PAIRS * DIN];               // W*64 hi split
__device__ __half g_Wl[PAIRS * DIN];               // W*64 lo split

// ---------------------------------------------------------------------------
// helpers
// ---------------------------------------------------------------------------
__device__ __forceinline__ uint32_t pkh(__half a, __half b) {
    __half2 t = __halves2half2(a, b);
    return *(uint32_t*)&t;
}

#define CP_ASYNC16(sm, gm) \
    asm volatile("cp.async.cg.shared.global [%0], [%1], 16;" :: "r"(sm), "l"(gm))
#define CP_COMMIT() asm volatile("cp.async.commit_group;" ::: "memory")
#define CP_WAIT0()  asm volatile("cp.async.wait_group 0;" ::: "memory")

// ---------------------------------------------------------------------------
// W split (scaled by 64; epilogue multiplies 1/64).
// ---------------------------------------------------------------------------
__global__ void wsplit_kernel(const float* __restrict__ W, int blk0) {
    int i4 = (blk0 + blockIdx.x) * 256 + threadIdx.x;
    if (i4 >= PAIRS * DIN / 4) return;
    float4 v = ((const float4*)W)[i4];
    float a[4] = {v.x * 64.f, v.y * 64.f, v.z * 64.f, v.w * 64.f};
    __half h[4], l[4];
#pragma unroll
    for (int e = 0; e < 4; e++) {
        h[e] = __float2half_rn(a[e]);
        l[e] = __float2half_rn(a[e] - __half2float(h[e]));
    }
    ((uint2*)g_Wh)[i4] = make_uint2(pkh(h[0], h[1]), pkh(h[2], h[3]));
    ((uint2*)g_Wl)[i4] = make_uint2(pkh(l[0], l[1]), pkh(l[2], l[3]));
}

// ---------------------------------------------------------------------------
// Tail copy: out[:,512:2048] = x[:,512:2048]. Runs before the gemm.
// ---------------------------------------------------------------------------
__global__ void copytail_kernel(const float* __restrict__ x, float* __restrict__ out) {
    size_t base = (size_t)blockIdx.x * (DIN / 4) + (512 / 4);
    const float4* xs = (const float4*)x + base;
    float4* os = (float4*)out + base;
#pragma unroll
    for (int k = 0; k < 3; k++)
        os[threadIdx.x + 128 * k] = xs[threadIdx.x + 128 * k];
}

// ---------------------------------------------------------------------------
// mma.sync GEMM: delta = X @ W^T (+bias), 3-product fp16 split.
// BM=64, BN=128, BK=32, 4 warps, warp tile 32x64, 3 CTAs/SM (12 warps/SM).
// W via cp.async; X converted in-loop. Fused epilogue: per-16-row chunk sums.
// ---------------------------------------------------------------------------
#define BM 64
#define BN 128
#define BK 32
#define NTHR 128
#define ROWH 40                    // halves per smem row (80 bytes)
#define A_REG (64 * ROWH)          // 2560 halves per A region
#define B_REG (128 * ROWH)         // 5120 halves per B region
#define ABASE (4 * A_REG)          // B regions start (halves)
#define SMEM_BYTES ((ABASE + 4 * B_REG) * 2)   // 61440 B

#define LDSM_X4(r0, r1, r2, r3, addr) \
    asm volatile("ldmatrix.sync.aligned.m8n8.x4.shared.b16 {%0,%1,%2,%3}, [%4];" \
                 : "=r"(r0), "=r"(r1), "=r"(r2), "=r"(r3) : "r"(addr))

#define MMA16816(d, a, b0, b1) \
    asm volatile("mma.sync.aligned.m16n8k16.row.col.f32.f16.f16.f32 " \
                 "{%0,%1,%2,%3}, {%4,%5,%6,%7}, {%8,%9}, {%0,%1,%2,%3};" \
                 : "+f"((d)[0]), "+f"((d)[1]), "+f"((d)[2]), "+f"((d)[3]) \
                 : "r"((a)[0]), "r"((a)[1]), "r"((a)[2]), "r"((a)[3]), \
                   "r"(b0), "r"(b1))

__global__ __launch_bounds__(NTHR, 3)
void gemm_kernel(const float* __restrict__ X, const float* __restrict__ bias) {
    extern __shared__ __half sh[];
    const int tid = threadIdx.x, lane = tid & 31, wid = tid >> 5;
    const int m0 = blockIdx.y * BM, n0 = blockIdx.x * BN;
    const int wm = (wid & 1) * 32, wn = (wid >> 1) * 64;
    const uint32_t sbase = (uint32_t)__cvta_generic_to_shared(sh);

    float acc[2][8][4];
#pragma unroll
    for (int i = 0; i < 2; i++)
#pragma unroll
        for (int j = 0; j < 8; j++)
#pragma unroll
            for (int r = 0; r < 4; r++) acc[i][j][r] = 0.f;

    float4 xa[4];

    // A tile: 64x32 fp32 = 512 float4, 4 per thread
#define LDG_X(k0) do {                                                         \
    _Pragma("unroll")                                                          \
    for (int i = 0; i < 4; i++) {                                              \
        int f = tid + i * NTHR; int r = f >> 3, q = f & 7;                     \
        xa[i] = *(const float4*)(X + (size_t)(m0 + r) * DIN + (k0) + q * 4);   \
    }                                                                          \
} while (0)

#define STS_X(buf) do {                                                        \
    _Pragma("unroll")                                                          \
    for (int i = 0; i < 4; i++) {                                              \
        int f = tid + i * NTHR; int r = f >> 3, q = f & 7;                     \
        float4 v = xa[i];                                                      \
        __half h0 = __float2half_rn(v.x), h1 = __float2half_rn(v.y);           \
        __half h2 = __float2half_rn(v.z), h3 = __float2half_rn(v.w);           \
        __half l0 = __float2half_rn(v.x - __half2float(h0));                   \
        __half l1 = __float2half_rn(v.y - __half2float(h1));                   \
        __half l2 = __float2half_rn(v.z - __half2float(h2));                   \
        __half l3 = __float2half_rn(v.w - __half2float(h3));                   \
        int off = r * ROWH + q * 4;                                            \
        *(uint2*)(sh + ((buf) * 2 + 0) * A_REG + off) =                        \
            make_uint2(pkh(h0, h1), pkh(h2, h3));                              \
        *(uint2*)(sh + ((buf) * 2 + 1) * A_REG + off) =                        \
            make_uint2(pkh(l0, l1), pkh(l2, l3));                              \
    }                                                                          \
} while (0)

    // B tile via cp.async: 2 splits x 128 rows x 4 x 16B = 1024 ops, 8/thread
#define CPA_W(buf, k0) do {                                                    \
    _Pragma("unroll")                                                          \
    for (int i = 0; i < 8; i++) {                                              \
        int f = tid + i * NTHR;                                                \
        int sp = f >> 9, idx = f & 511;                                        \
        int r = idx >> 2, q = idx & 3;                                         \
        const __half* src = (sp ? g_Wl : g_Wh) + (size_t)(n0 + r) * DIN + (k0) + q * 8; \
        uint32_t dst = sbase + (ABASE + ((buf) * 2 + sp) * B_REG + r * ROWH + q * 8) * 2; \
        CP_ASYNC16(dst, src);                                                  \
    }                                                                          \
} while (0)

    // prologue
    CPA_W(0, 0);
    CP_COMMIT();
    LDG_X(0);
    STS_X(0);
    CP_WAIT0();
    __syncthreads();

    for (int c = 0; c < DIN / BK; c++) {
        const int buf = c & 1;
        if (c + 1 < DIN / BK) {
            LDG_X((c + 1) * BK);
            CPA_W(buf ^ 1, (c + 1) * BK);
            CP_COMMIT();
        }

#pragma unroll
        for (int kk = 0; kk < 2; kk++) {
            uint32_t ah[2][2][4];   // [split][m16 block][reg]
            uint32_t bh[2][4][4];   // [split][n16 group][reg]
#pragma unroll
            for (int s = 0; s < 2; s++) {
                uint32_t areg = sbase + ((buf * 2 + s) * A_REG) * 2;
#pragma unroll
                for (int i = 0; i < 2; i++) {
                    int row = wm + i * 16 + (lane & 15);
                    int col = kk * 16 + ((lane >> 4) << 3);
                    LDSM_X4(ah[s][i][0], ah[s][i][1], ah[s][i][2], ah[s][i][3],
                            areg + row * 80 + col * 2);
                }
                uint32_t breg = sbase + (ABASE + (buf * 2 + s) * B_REG) * 2;
#pragma unroll
                for (int j = 0; j < 4; j++) {
                    int grp = lane >> 3, ii = lane & 7;
                    int row = wn + j * 16 + ((grp >> 1) << 3) + ii;
                    int col = kk * 16 + ((grp & 1) << 3);
                    LDSM_X4(bh[s][j][0], bh[s][j][1], bh[s][j][2], bh[s][j][3],
                            breg + row * 80 + col * 2);
                }
            }
#pragma unroll
            for (int i = 0; i < 2; i++)
#pragma unroll
                for (int jt = 0; jt < 8; jt++) {
                    uint32_t b0h = bh[0][jt >> 1][(jt & 1) * 2];
                    uint32_t b1h = bh[0][jt >> 1][(jt & 1) * 2 + 1];
                    uint32_t b0l = bh[1][jt >> 1][(jt & 1) * 2];
                    uint32_t b1l = bh[1][jt >> 1][(jt & 1) * 2 + 1];
                    MMA16816(acc[i][jt], ah[0][i], b0h, b1h);   // Xh*Wh
                    MMA16816(acc[i][jt], ah[0][i], b0l, b1l);   // Xh*Wl
                    MMA16816(acc[i][jt], ah[1][i], b0h, b1h);   // Xl*Wh
                }
        }

        if (c + 1 < DIN / BK) {
            STS_X(buf ^ 1);
            CP_WAIT0();
        }
        __syncthreads();
    }

    // ---- epilogue 1: undo W*64 scale, add bias, write g_delta ----
    const float inv64 = 0.015625f;
#pragma unroll
    for (int i = 0; i < 2; i++) {
        int row = m0 + wm + i * 16 + (lane >> 2);
#pragma unroll
        for (int jt = 0; jt < 8; jt++) {
            int col = n0 + wn + jt * 8 + (lane & 3) * 2;
            float2 bv = *(const float2*)(bias + col);
            float2 o0, o1;
            o0.x = acc[i][jt][0] * inv64 + bv.x;
            o0.y = acc[i][jt][1] * inv64 + bv.y;
            o1.x = acc[i][jt][2] * inv64 + bv.x;
            o1.y = acc[i][jt][3] * inv64 + bv.y;
            *(float2*)(g_delta + (size_t)row * PAIRS + col) = o0;
            *(float2*)(g_delta + (size_t)(row + 8) * PAIRS + col) = o1;
        }
    }

    // ---- epilogue 2: fused chunk sums (chunk = 16 rows = one m16 block) ----
    int b = m0 >> 12;
    int cbase = ((m0 & (SEQ - 1)) >> 4) + (wm >> 4);
#pragma unroll
    for (int i = 0; i < 2; i++) {
        float s[8][2];
#pragma unroll
        for (int jt = 0; jt < 8; jt++)
#pragma unroll
            for (int cp = 0; cp < 2; cp++) {
                float v = acc[i][jt][cp] + acc[i][jt][2 + cp];
#pragma unroll
                for (int d = 4; d < 32; d <<= 1)
                    v += __shfl_xor_sync(0xFFFFFFFFu, v, d);
                s[jt][cp] = v;
            }
        if (lane < 4) {
#pragma unroll
            for (int jt = 0; jt < 8; jt++) {
                int col = n0 + wn + jt * 8 + lane * 2;
                float2 bv = *(const float2*)(bias + col);
                float2 o;
                o.x = s[jt][0] * inv64 + 16.f * bv.x;
                o.y = s[jt][1] * inv64 + 16.f * bv.y;
                *(float2*)(g_csum + (size_t)(b * NCHUNK + cbase + i) * PAIRS + col) = o;
            }
        }
    }
#undef LDG_X
#undef STS_X
#undef CPA_W
}

// ---------------------------------------------------------------------------
// Chunk scan: warp per (b,p), shfl exclusive scan over 256 chunks (8/lane).
// ---------------------------------------------------------------------------
__global__ void chunkscan_kernel() {
    int gw = (blockIdx.x * blockDim.x + threadIdx.x) >> 5;  // 0..1023
    int b = gw >> 8, p = gw & 255;
    int lane = threadIdx.x & 31;
    const float* src = g_csum + (size_t)b * NCHUNK * PAIRS + p;
    float* dst = g_coff + (size_t)b * NCHUNK * PAIRS + p;
    float v[8], s[8];
    float run = 0.f;
#pragma unroll
    for (int j = 0; j < 8; j++) {
        v[j] = src[(size_t)(lane * 8 + j) * PAIRS];
        run += v[j];
        s[j] = run;
    }
    float tot = run;
#pragma unroll
    for (int d = 1; d < 32; d <<= 1) {
        float o = __shfl_up_sync(0xFFFFFFFFu, run, d);
        if (lane >= d) run += o;
    }
    float excl = run - tot;
#pragma unroll
    for (int j = 0; j < 8; j++)
        dst[(size_t)(lane * 8 + j) * PAIRS] = excl + s[j] - v[j];
}

// ---------------------------------------------------------------------------
// Accurate large-range sincos (Cody-Waite 3-term 2pi reduction)
// ---------------------------------------------------------------------------
__device__ __forceinline__ void accurate_sincos(float ang, float* sn, float* cs) {
    const float INV_2PI = 0.15915494309189535f;
    const float C1 = 6.28125f;
    const float C2 = 1.9353071795e-3f;
    const float C3 = 3.1786509424591713e-8f;
    float n = rintf(ang * INV_2PI);
    float r = ang - n * C1;
    r = r - n * C2;
    r = r - n * C3;
    *sn = sinf(r);
    *cs = cosf(r);
}

// ---------------------------------------------------------------------------
// Rotate: local scan + rotation only (tail copied by copytail_kernel).
// ---------------------------------------------------------------------------
__global__ void rotate_kernel(const float* __restrict__ x, float* __restrict__ out) {
    int bc = blockIdx.x;
    int b = bc >> 8, c = bc & 255;
    int p = threadIdx.x;
    float angle = g_coff[(size_t)bc * PAIRS + p];
    int t0 = b * SEQ + c * TCHUNK;
    for (int i = 0; i < TCHUNK; i++) {
        int t = t0 + i;
        angle += g_delta[(size_t)t * PAIRS + p];
        float sn, cs;
        accurate_sincos(angle, &sn, &cs);
        const float* xr = x + (size_t)t * DIN;
        float* orow = out + (size_t)t * DIN;
        float x1 = xr[p];
        float x2 = xr[PAIRS + p];
        orow[p]         = x1 * cs - x2 * sn;
        orow[PAIRS + p] = x2 * cs + x1 * sn;
    }
}

extern "C" void kernel_launch(void* const* d_in, const int* in_sizes, int n_in,
                              void* d_out, int out_size) {
    const float* x    = (const float*)d_in[0];
    const float* W    = (const float*)d_in[1];
    const float* bias = (const float*)d_in[2];
    float* out = (float*)d_out;

    cudaFuncSetAttribute(gemm_kernel, cudaFuncAttributeMaxDynamicSharedMemorySize,
                         SMEM_BYTES);

    wsplit_kernel<<<256, 256>>>(W, 0);
    wsplit_kernel<<<256, 256>>>(W, 256);
    copytail_kernel<<<MROWS, 128>>>(x, out);
    gemm_kernel<<<dim3(PAIRS / BN, MROWS / BM), NTHR, SMEM_BYTES>>>(x, bias);
    chunkscan_kernel<<<128, 256>>>();
    rotate_kernel<<<BATCH * NCHUNK, 256>>>(x, out);
}

// round 16
// speedup vs baseline: 1.1016x; 1.1016x over previous
#include <cuda_runtime.h>
#include <cuda_fp16.h>
#include <math.h>
#include <cstdint>

// ---------------------------------------------------------------------------
// Problem constants
// ---------------------------------------------------------------------------
#define BATCH 4
#define SEQ   4096
#define DIN   2048
#define PAIRS 256
#define MROWS (BATCH*SEQ)      // 16384
#define NCHUNK 256
#define TCHUNK (SEQ/NCHUNK)    // 16

// Scratch (device globals: no allocation allowed)
__device__ float g_delta[MROWS * PAIRS];           // 16.8 MB [m][p]
__device__ float g_csum [BATCH * NCHUNK * PAIRS];  // [b][c][p]
__device__ float g_coff [BATCH * NCHUNK * PAIRS];  // [b][c][p]
__device__ __half g_Wh[PAIRS * DIN];               // W*64 hi split
__device__ __half g_Wl[PAIRS * DIN];               // W*64 lo split

// ---------------------------------------------------------------------------
// fp16 helpers
// ---------------------------------------------------------------------------
__device__ __forceinline__ uint32_t pkh(__half a, __half b) {
    __half2 t = __halves2half2(a, b);
    return *(uint32_t*)&t;
}

// ---------------------------------------------------------------------------
// W split (scaled by 64; epilogue multiplies 1/64).
// ---------------------------------------------------------------------------
__global__ void wsplit_kernel(const float* __restrict__ W, int blk0) {
    int i4 = (blk0 + blockIdx.x) * 256 + threadIdx.x;
    if (i4 >= PAIRS * DIN / 4) return;
    float4 v = ((const float4*)W)[i4];
    float a[4] = {v.x * 64.f, v.y * 64.f, v.z * 64.f, v.w * 64.f};
    __half h[4], l[4];
#pragma unroll
    for (int e = 0; e < 4; e++) {
        h[e] = __float2half_rn(a[e]);
        l[e] = __float2half_rn(a[e] - __half2float(h[e]));
    }
    ((uint2*)g_Wh)[i4] = make_uint2(pkh(h[0], h[1]), pkh(h[2], h[3]));
    ((uint2*)g_Wl)[i4] = make_uint2(pkh(l[0], l[1]), pkh(l[2], l[3]));
}

// ---------------------------------------------------------------------------
// Tail copy: out[:,512:2048] = x[:,512:2048]. Runs on a forked stream,
// concurrent with wsplit+gemm (disjoint from rotate's out[:,:512]).
// ---------------------------------------------------------------------------
__global__ void copytail_kernel(const float* __restrict__ x, float* __restrict__ out) {
    size_t base = (size_t)blockIdx.x * (DIN / 4) + (512 / 4);
    const float4* xs = (const float4*)x + base;
    float4* os = (float4*)out + base;
#pragma unroll
    for (int k = 0; k < 3; k++)
        os[threadIdx.x + 128 * k] = xs[threadIdx.x + 128 * k];
}

// ---------------------------------------------------------------------------
// mma.sync GEMM: delta = X @ W^T (+bias), 3-product fp16 split.
// BM=128, BN=128, BK=32, 8 warps (2x4), warp tile 64x32 (frozen R5 mainloop).
// Fused epilogue: per-16-row chunk sums.
// ---------------------------------------------------------------------------
#define BM 128
#define BN 128
#define BK 32
#define ROWH 40                 // halves per smem row (80 bytes)
#define REGH (128 * ROWH)       // halves per (buf,split) region = 5120
#define SMEM_BYTES (8 * REGH * 2)  // 81920 B

#define LDSM_X4(r0, r1, r2, r3, addr) \
    asm volatile("ldmatrix.sync.aligned.m8n8.x4.shared.b16 {%0,%1,%2,%3}, [%4];" \
                 : "=r"(r0), "=r"(r1), "=r"(r2), "=r"(r3) : "r"(addr))

#define MMA16816(d, a, b0, b1) \
    asm volatile("mma.sync.aligned.m16n8k16.row.col.f32.f16.f16.f32 " \
                 "{%0,%1,%2,%3}, {%4,%5,%6,%7}, {%8,%9}, {%0,%1,%2,%3};" \
                 : "+f"((d)[0]), "+f"((d)[1]), "+f"((d)[2]), "+f"((d)[3]) \
                 : "r"((a)[0]), "r"((a)[1]), "r"((a)[2]), "r"((a)[3]), \
                   "r"(b0), "r"(b1))

__global__ __launch_bounds__(256, 1)
void gemm_kernel(const float* __restrict__ X, const float* __restrict__ bias) {
    extern __shared__ __half sh[];
    const int tid = threadIdx.x, lane = tid & 31, wid = tid >> 5;
    const int m0 = blockIdx.y * BM, n0 = blockIdx.x * BN;
    const int wm = (wid & 1) * 64, wn = (wid >> 1) * 32;
    const uint32_t sbase = (uint32_t)__cvta_generic_to_shared(sh);

    float acc[4][4][4];
#pragma unroll
    for (int i = 0; i < 4; i++)
#pragma unroll
        for (int j = 0; j < 4; j++)
#pragma unroll
            for (int r = 0; r < 4; r++) acc[i][j][r] = 0.f;

    float4 xa[4];
    uint4 wreg[2][2];

#define LDG_TILE(k0) do {                                                      \
    _Pragma("unroll")                                                          \
    for (int i = 0; i < 4; i++) {                                              \
        int f = tid + i * 256; int r = f >> 3, q = f & 7;                      \
        xa[i] = *(const float4*)(X + (size_t)(m0 + r) * DIN + (k0) + q * 4);   \
    }                                                                          \
    _Pragma("unroll")                                                          \
    for (int i = 0; i < 2; i++) {                                              \
        int f = tid + i * 256; int r = f >> 2, q = f & 3;                      \
        wreg[0][i] = *(const uint4*)(g_Wh + (size_t)(n0 + r) * DIN + (k0) + q * 8); \
        wreg[1][i] = *(const uint4*)(g_Wl + (size_t)(n0 + r) * DIN + (k0) + q * 8); \
    }                                                                          \
} while (0)

#define STS_TILE(buf) do {                                                     \
    _Pragma("unroll")                                                          \
    for (int i = 0; i < 4; i++) {                                              \
        int f = tid + i * 256; int r = f >> 3, q = f & 7;                      \
        float4 v = xa[i];                                                      \
        __half h0 = __float2half_rn(v.x), h1 = __float2half_rn(v.y);           \
        __half h2 = __float2half_rn(v.z), h3 = __float2half_rn(v.w);           \
        __half l0 = __float2half_rn(v.x - __half2float(h0));                   \
        __half l1 = __float2half_rn(v.y - __half2float(h1));                   \
        __half l2 = __float2half_rn(v.z - __half2float(h2));                   \
        __half l3 = __float2half_rn(v.w - __half2float(h3));                   \
        int off = r * ROWH + q * 4;                                            \
        *(uint2*)(sh + ((buf) * 2 + 0) * REGH + off) =                         \
            make_uint2(pkh(h0, h1), pkh(h2, h3));                              \
        *(uint2*)(sh + ((buf) * 2 + 1) * REGH + off) =                         \
            make_uint2(pkh(l0, l1), pkh(l2, l3));                              \
    }                                                                          \
    _Pragma("unroll")                                                          \
    for (int i = 0; i < 2; i++) {                                              \
        int f = tid + i * 256; int r = f >> 2, q = f & 3;                      \
        int off = r * ROWH + q * 8;                                            \
        *(uint4*)(sh + (4 + (buf) * 2 + 0) * REGH + off) = wreg[0][i];         \
        *(uint4*)(sh + (4 + (buf) * 2 + 1) * REGH + off) = wreg[1][i];         \
    }                                                                          \
} while (0)

    LDG_TILE(0);
    STS_TILE(0);
    __syncthreads();

    for (int c = 0; c < DIN / BK; c++) {
        const int buf = c & 1;
        if (c + 1 < DIN / BK) LDG_TILE((c + 1) * BK);

#pragma unroll
        for (int kk = 0; kk < 2; kk++) {
            uint32_t ah[2][4][4];
            uint32_t bh[2][2][4];
#pragma unroll
            for (int s = 0; s < 2; s++) {
                uint32_t areg = sbase + ((buf * 2 + s) * REGH) * 2;
#pragma unroll
                for (int i = 0; i < 4; i++) {
                    int row = wm + i * 16 + (lane & 15);
                    int col = kk * 16 + ((lane >> 4) << 3);
                    LDSM_X4(ah[s][i][0], ah[s][i][1], ah[s][i][2], ah[s][i][3],
                            areg + row * 80 + col * 2);
                }
                uint32_t breg = sbase + ((4 + buf * 2 + s) * REGH) * 2;
#pragma unroll
                for (int j = 0; j < 2; j++) {
                    int grp = lane >> 3, ii = lane & 7;
                    int row = wn + j * 16 + ((grp >> 1) << 3) + ii;
                    int col = kk * 16 + ((grp & 1) << 3);
                    LDSM_X4(bh[s][j][0], bh[s][j][1], bh[s][j][2], bh[s][j][3],
                            breg + row * 80 + col * 2);
                }
            }
#pragma unroll
            for (int i = 0; i < 4; i++)
#pragma unroll
                for (int jt = 0; jt < 4; jt++) {
                    uint32_t b0h = bh[0][jt >> 1][(jt & 1) * 2];
                    uint32_t b1h = bh[0][jt >> 1][(jt & 1) * 2 + 1];
                    uint32_t b0l = bh[1][jt >> 1][(jt & 1) * 2];
                    uint32_t b1l = bh[1][jt >> 1][(jt & 1) * 2 + 1];
                    MMA16816(acc[i][jt], ah[0][i], b0h, b1h);   // Xh*Wh
                    MMA16816(acc[i][jt], ah[0][i], b0l, b1l);   // Xh*Wl
                    MMA16816(acc[i][jt], ah[1][i], b0h, b1h);   // Xl*Wh
                }
        }

        if (c + 1 < DIN / BK) STS_TILE(buf ^ 1);
        __syncthreads();
    }

    // ---- epilogue 1: undo W*64 scale, add bias, write g_delta ----
    const float inv64 = 0.015625f;
#pragma unroll
    for (int i = 0; i < 4; i++) {
        int row = m0 + wm + i * 16 + (lane >> 2);
#pragma unroll
        for (int jt = 0; jt < 4; jt++) {
            int col = n0 + wn + jt * 8 + (lane & 3) * 2;
            float2 bv = *(const float2*)(bias + col);
            float2 o0, o1;
            o0.x = acc[i][jt][0] * inv64 + bv.x;
            o0.y = acc[i][jt][1] * inv64 + bv.y;
            o1.x = acc[i][jt][2] * inv64 + bv.x;
            o1.y = acc[i][jt][3] * inv64 + bv.y;
            *(float2*)(g_delta + (size_t)row * PAIRS + col) = o0;
            *(float2*)(g_delta + (size_t)(row + 8) * PAIRS + col) = o1;
        }
    }

    // ---- epilogue 2: fused chunk sums (chunk = 16 rows = one m16 block) ----
    int b = m0 >> 12;
    int cbase = ((m0 & (SEQ - 1)) >> 4) + (wm >> 4);
#pragma unroll
    for (int i = 0; i < 4; i++) {
        float s[4][2];
#pragma unroll
        for (int jt = 0; jt < 4; jt++)
#pragma unroll
            for (int cp = 0; cp < 2; cp++) {
                float v = acc[i][jt][cp] + acc[i][jt][2 + cp];
#pragma unroll
                for (int d = 4; d < 32; d <<= 1)
                    v += __shfl_xor_sync(0xFFFFFFFFu, v, d);
                s[jt][cp] = v;
            }
        if (lane < 4) {
#pragma unroll
            for (int jt = 0; jt < 4; jt++) {
                int col = n0 + wn + jt * 8 + lane * 2;
                float2 bv = *(const float2*)(bias + col);
                float2 o;
                o.x = s[jt][0] * inv64 + 16.f * bv.x;
                o.y = s[jt][1] * inv64 + 16.f * bv.y;
                *(float2*)(g_csum + (size_t)(b * NCHUNK + cbase + i) * PAIRS + col) = o;
            }
        }
    }
#undef LDG_TILE
#undef STS_TILE
}

// ---------------------------------------------------------------------------
// Chunk scan: warp per (b,p), shfl exclusive scan over 256 chunks (8/lane).
// ---------------------------------------------------------------------------
__global__ void chunkscan_kernel() {
    int gw = (blockIdx.x * blockDim.x + threadIdx.x) >> 5;  // 0..1023
    int b = gw >> 8, p = gw & 255;
    int lane = threadIdx.x & 31;
    const float* src = g_csum + (size_t)b * NCHUNK * PAIRS + p;
    float* dst = g_coff + (size_t)b * NCHUNK * PAIRS + p;
    float v[8], s[8];
    float run = 0.f;
#pragma unroll
    for (int j = 0; j < 8; j++) {
        v[j] = src[(size_t)(lane * 8 + j) * PAIRS];
        run += v[j];
        s[j] = run;
    }
    float tot = run;
#pragma unroll
    for (int d = 1; d < 32; d <<= 1) {
        float o = __shfl_up_sync(0xFFFFFFFFu, run, d);
        if (lane >= d) run += o;
    }
    float excl = run - tot;
#pragma unroll
    for (int j = 0; j < 8; j++)
        dst[(size_t)(lane * 8 + j) * PAIRS] = excl + s[j] - v[j];
}

// ---------------------------------------------------------------------------
// Accurate large-range sincos (Cody-Waite 3-term 2pi reduction)
// ---------------------------------------------------------------------------
__device__ __forceinline__ void accurate_sincos(float ang, float* sn, float* cs) {
    const float INV_2PI = 0.15915494309189535f;
    const float C1 = 6.28125f;
    const float C2 = 1.9353071795e-3f;
    const float C3 = 3.1786509424591713e-8f;
    float n = rintf(ang * INV_2PI);
    float r = ang - n * C1;
    r = r - n * C2;
    r = r - n * C3;
    *sn = sinf(r);
    *cs = cosf(r);
}

// ---------------------------------------------------------------------------
// Rotate: local scan + rotation only (tail copied by copytail_kernel).
// ---------------------------------------------------------------------------
__global__ void rotate_kernel(const float* __restrict__ x, float* __restrict__ out) {
    int bc = blockIdx.x;
    int b = bc >> 8, c = bc & 255;
    int p = threadIdx.x;
    float angle = g_coff[(size_t)bc * PAIRS + p];
    int t0 = b * SEQ + c * TCHUNK;
    for (int i = 0; i < TCHUNK; i++) {
        int t = t0 + i;
        angle += g_delta[(size_t)t * PAIRS + p];
        float sn, cs;
        accurate_sincos(angle, &sn, &cs);
        const float* xr = x + (size_t)t * DIN;
        float* orow = out + (size_t)t * DIN;
        float x1 = xr[p];
        float x2 = xr[PAIRS + p];
        orow[p]         = x1 * cs - x2 * sn;
        orow[PAIRS + p] = x2 * cs + x1 * sn;
    }
}

extern "C" void kernel_launch(void* const* d_in, const int* in_sizes, int n_in,
                              void* d_out, int out_size) {
    const float* x    = (const float*)d_in[0];
    const float* W    = (const float*)d_in[1];
    const float* bias = (const float*)d_in[2];
    float* out = (float*)d_out;

    cudaFuncSetAttribute(gemm_kernel, cudaFuncAttributeMaxDynamicSharedMemorySize,
                         SMEM_BYTES);

    // Fork a side stream for the independent tail copy (graph-capturable
    // fork/join: event-record on capture stream, wait on side stream, and
    // join back before returning).
    cudaStream_t s2;
    cudaStreamCreateWithFlags(&s2, cudaStreamNonBlocking);
    cudaEvent_t eFork, eJoin;
    cudaEventCreateWithFlags(&eFork, cudaEventDisableTiming);
    cudaEventCreateWithFlags(&eJoin, cudaEventDisableTiming);

    cudaEventRecord(eFork, 0);
    cudaStreamWaitEvent(s2, eFork, 0);
    copytail_kernel<<<MROWS, 128, 0, s2>>>(x, out);     // concurrent with gemm
    cudaEventRecord(eJoin, s2);

    wsplit_kernel<<<256, 256>>>(W, 0);
    wsplit_kernel<<<256, 256>>>(W, 256);
    gemm_kernel<<<dim3(PAIRS / BN, MROWS / BM), 256, SMEM_BYTES>>>(x, bias);
    chunkscan_kernel<<<128, 256>>>();
    rotate_kernel<<<BATCH * NCHUNK, 256>>>(x, out);

    cudaStreamWaitEvent(0, eJoin, 0);                    // rejoin before return

    cudaEventDestroy(eFork);
    cudaEventDestroy(eJoin);
    cudaStreamDestroy(s2);
}